// round 14
// baseline (speedup 1.0000x reference)
#include <cuda_runtime.h>
#include <cuda_bf16.h>

// Snack: out[p] = tanh((f[i]-f[j])^T M (f[i]-f[j])), P = 8,388,608, 20 AAs.
// Fused persistent kernel (R12 winner + 256-bit evict_last idx loads):
//   - symmetric table build: 190 pairs, diag=0, mirrored; 512-thr blocks
//   - idx loads: ld.global.nc.L2::evict_last.v8.b32 (32B per load; the only
//     form ptxas accepts the L2 hint on for sm_103). Retain the 64MB idx
//     streams in L2 across graph replays.
//   - out stores: st.global.cs (evict-first write-once stream)
//   - ILP-2 groups of 8 pairs -> 4 LDG.256 in flight per thread.

#define NUM_AA   20
#define FEAT_DIM 16
#define FPAD     17
#define TBL      (NUM_AA * NUM_AA)
#define NPAIRS   190
#define THREADS  512
#define NF       (NUM_AA * FEAT_DIM)   // 320

struct I8 { int v[8]; };

__device__ __forceinline__ I8 ldg_keep8(const int* p) {
    I8 r;
    asm volatile("ld.global.nc.L2::evict_last.v8.b32 "
                 "{%0,%1,%2,%3,%4,%5,%6,%7}, [%8];"
                 : "=r"(r.v[0]), "=r"(r.v[1]), "=r"(r.v[2]), "=r"(r.v[3]),
                   "=r"(r.v[4]), "=r"(r.v[5]), "=r"(r.v[6]), "=r"(r.v[7])
                 : "l"(p));
    return r;
}

__global__ __launch_bounds__(THREADS, 3) void snack_fused_kernel(
    const float*  __restrict__ features,   // [20, 16]
    const float*  __restrict__ M,          // [16, 16]
    const int*    __restrict__ idx_i,      // [P]
    const int*    __restrict__ idx_j,      // [P]
    float4*       __restrict__ out4,       // [P/4]
    int n8)                                 // P/8 groups of 8
{
    __shared__ float s_F[NUM_AA * FPAD];
    __shared__ float s_M[FEAT_DIM * FEAT_DIM];
    __shared__ float s_FM[NUM_AA * FPAD];
    __shared__ float s_tbl[TBL];

    const int t = threadIdx.x;

    for (int k = t; k < NF; k += THREADS) {
        const int r = k >> 4, c = k & 15;
        s_F[r * FPAD + c] = features[k];
    }
    for (int k = t; k < FEAT_DIM * FEAT_DIM; k += THREADS) s_M[k] = M[k];
    if (t < NUM_AA) s_tbl[t * NUM_AA + t] = 0.0f;   // tanh(0) == 0 exactly
    __syncthreads();

    for (int k = t; k < NF; k += THREADS) {
        const int r = k >> 4, c = k & 15;
        float acc = 0.0f;
#pragma unroll
        for (int y = 0; y < FEAT_DIM; y++)
            acc = fmaf(s_F[r * FPAD + y], s_M[y * FEAT_DIM + c], acc);
        s_FM[r * FPAD + c] = acc;
    }
    __syncthreads();

    if (t < NPAIRS) {
        int i = 0, rem = t;
        while (rem >= NUM_AA - 1 - i) { rem -= NUM_AA - 1 - i; i++; }
        const int j = i + 1 + rem;

        float gii = 0.0f, gij = 0.0f, gji = 0.0f, gjj = 0.0f;
#pragma unroll
        for (int y = 0; y < FEAT_DIM; y++) {
            const float fiy  = s_F[i * FPAD + y];
            const float fjy  = s_F[j * FPAD + y];
            const float fmiy = s_FM[i * FPAD + y];
            const float fmjy = s_FM[j * FPAD + y];
            gii = fmaf(fmiy, fiy, gii);
            gij = fmaf(fmiy, fjy, gij);
            gji = fmaf(fmjy, fiy, gji);
            gjj = fmaf(fmjy, fjy, gjj);
        }
        const float v = tanhf(gii - gij - gji + gjj);
        s_tbl[i * NUM_AA + j] = v;
        s_tbl[j * NUM_AA + i] = v;
    }
    __syncthreads();

    // Gather: each "group" = 8 consecutive pairs (one 32B v8 load per array).
    // ILP-2 groups -> 4 LDG.256 in flight per thread.
    const int stride = gridDim.x * THREADS;   // in groups
    int g = blockIdx.x * THREADS + t;

    for (; g + stride < n8; g += 2 * stride) {
        const int g0 = g, g1 = g + stride;
        I8 a0 = ldg_keep8(&idx_i[g0 * 8]);
        I8 b0 = ldg_keep8(&idx_j[g0 * 8]);
        I8 a1 = ldg_keep8(&idx_i[g1 * 8]);
        I8 b1 = ldg_keep8(&idx_j[g1 * 8]);

        float4 o;
        o.x = s_tbl[a0.v[0] * NUM_AA + b0.v[0]];
        o.y = s_tbl[a0.v[1] * NUM_AA + b0.v[1]];
        o.z = s_tbl[a0.v[2] * NUM_AA + b0.v[2]];
        o.w = s_tbl[a0.v[3] * NUM_AA + b0.v[3]];
        __stcs(&out4[g0 * 2], o);
        o.x = s_tbl[a0.v[4] * NUM_AA + b0.v[4]];
        o.y = s_tbl[a0.v[5] * NUM_AA + b0.v[5]];
        o.z = s_tbl[a0.v[6] * NUM_AA + b0.v[6]];
        o.w = s_tbl[a0.v[7] * NUM_AA + b0.v[7]];
        __stcs(&out4[g0 * 2 + 1], o);

        o.x = s_tbl[a1.v[0] * NUM_AA + b1.v[0]];
        o.y = s_tbl[a1.v[1] * NUM_AA + b1.v[1]];
        o.z = s_tbl[a1.v[2] * NUM_AA + b1.v[2]];
        o.w = s_tbl[a1.v[3] * NUM_AA + b1.v[3]];
        __stcs(&out4[g1 * 2], o);
        o.x = s_tbl[a1.v[4] * NUM_AA + b1.v[4]];
        o.y = s_tbl[a1.v[5] * NUM_AA + b1.v[5]];
        o.z = s_tbl[a1.v[6] * NUM_AA + b1.v[6]];
        o.w = s_tbl[a1.v[7] * NUM_AA + b1.v[7]];
        __stcs(&out4[g1 * 2 + 1], o);
    }
    for (; g < n8; g += stride) {
        I8 a = ldg_keep8(&idx_i[g * 8]);
        I8 b = ldg_keep8(&idx_j[g * 8]);
        float4 o;
        o.x = s_tbl[a.v[0] * NUM_AA + b.v[0]];
        o.y = s_tbl[a.v[1] * NUM_AA + b.v[1]];
        o.z = s_tbl[a.v[2] * NUM_AA + b.v[2]];
        o.w = s_tbl[a.v[3] * NUM_AA + b.v[3]];
        __stcs(&out4[g * 2], o);
        o.x = s_tbl[a.v[4] * NUM_AA + b.v[4]];
        o.y = s_tbl[a.v[5] * NUM_AA + b.v[5]];
        o.z = s_tbl[a.v[6] * NUM_AA + b.v[6]];
        o.w = s_tbl[a.v[7] * NUM_AA + b.v[7]];
        __stcs(&out4[g * 2 + 1], o);
    }
}

extern "C" void kernel_launch(void* const* d_in, const int* in_sizes, int n_in,
                              void* d_out, int out_size)
{
    const float* features = (const float*)d_in[0];   // [20,16]
    const float* M        = (const float*)d_in[1];   // [16,16]
    const int*   idx_i    = (const int*)d_in[2];     // [P]
    const int*   idx_j    = (const int*)d_in[3];     // [P]
    float*       out      = (float*)d_out;           // [P]

    const int P  = out_size;   // 8,388,608
    const int n8 = P / 8;      // 1,048,576

    static int blocks = 0;
    if (blocks == 0) {
        int per_sm = 0;
        cudaOccupancyMaxActiveBlocksPerMultiprocessor(
            &per_sm, snack_fused_kernel, THREADS, 0);
        if (per_sm < 1) per_sm = 1;
        int sms = 0;
        cudaDeviceGetAttribute(&sms, cudaDevAttrMultiProcessorCount, 0);
        if (sms <= 0) sms = 148;
        blocks = per_sm * sms;
        int max_blocks = (n8 + THREADS - 1) / THREADS;
        if (blocks > max_blocks) blocks = max_blocks;
    }

    snack_fused_kernel<<<blocks, THREADS>>>(
        features, M, idx_i, idx_j, (float4*)out, n8);
}

// round 15
// speedup vs baseline: 1.1189x; 1.1189x over previous
#include <cuda_runtime.h>
#include <cuda_bf16.h>

// Snack: out[p] = tanh((f[i]-f[j])^T M (f[i]-f[j])), P = 8,388,608, 20 AAs.
// Final converged kernel (R12 configuration — measured 15.1us):
//   - SYMMETRY: dist(i,j)=dist(j,i) for any M; dist(i,i)=0 exactly.
//     -> only 190 strictly-upper pairs computed, mirrored; diag = 0.
//   - 512-thread blocks, 3 CTAs/SM -> minimal redundant per-CTA build
//     at 48 warps/SM for the gather.
//   - factorized G = (F M) F^T; dist = G[ii]-G[ij]-G[ji]+G[jj]
//   - batched ILP-4 gather (8 LDG.128 in flight) — best measured shape.
// Verified-at-floor: ~70MB effective DRAM traffic (partial L2 retention
// across graph replays) at ~6.3TB/s LTS ceiling + latency => ~15us.

#define NUM_AA   20
#define FEAT_DIM 16
#define FPAD     17
#define TBL      (NUM_AA * NUM_AA)
#define NPAIRS   190                   // 20*19/2 strictly upper
#define THREADS  512
#define NF       (NUM_AA * FEAT_DIM)   // 320

__global__ __launch_bounds__(THREADS, 3) void snack_fused_kernel(
    const float*  __restrict__ features,   // [20, 16]
    const float*  __restrict__ M,          // [16, 16]
    const int4*   __restrict__ idx_i4,     // [P/4]
    const int4*   __restrict__ idx_j4,     // [P/4]
    float4*       __restrict__ out4,       // [P/4]
    int n4)
{
    __shared__ float s_F[NUM_AA * FPAD];
    __shared__ float s_M[FEAT_DIM * FEAT_DIM];
    __shared__ float s_FM[NUM_AA * FPAD];
    __shared__ float s_tbl[TBL];

    const int t = threadIdx.x;

    // Stage F (padded) and M.
    for (int k = t; k < NF; k += THREADS) {
        const int r = k >> 4, c = k & 15;
        s_F[r * FPAD + c] = features[k];
    }
    for (int k = t; k < FEAT_DIM * FEAT_DIM; k += THREADS) s_M[k] = M[k];
    if (t < NUM_AA) s_tbl[t * NUM_AA + t] = 0.0f;   // tanh(0) == 0 exactly
    __syncthreads();

    // FM = F @ M (320 elements).
    for (int k = t; k < NF; k += THREADS) {
        const int r = k >> 4, c = k & 15;
        float acc = 0.0f;
#pragma unroll
        for (int y = 0; y < FEAT_DIM; y++)
            acc = fmaf(s_F[r * FPAD + y], s_M[y * FEAT_DIM + c], acc);
        s_FM[r * FPAD + c] = acc;
    }
    __syncthreads();

    // 190 strictly-upper pairs; mirror into (i,j) and (j,i).
    if (t < NPAIRS) {
        int i = 0, rem = t;
        while (rem >= NUM_AA - 1 - i) { rem -= NUM_AA - 1 - i; i++; }
        const int j = i + 1 + rem;

        float gii = 0.0f, gij = 0.0f, gji = 0.0f, gjj = 0.0f;
#pragma unroll
        for (int y = 0; y < FEAT_DIM; y++) {
            const float fiy  = s_F[i * FPAD + y];
            const float fjy  = s_F[j * FPAD + y];
            const float fmiy = s_FM[i * FPAD + y];
            const float fmjy = s_FM[j * FPAD + y];
            gii = fmaf(fmiy, fiy, gii);
            gij = fmaf(fmiy, fjy, gij);
            gji = fmaf(fmjy, fiy, gji);
            gjj = fmaf(fmjy, fjy, gjj);
        }
        const float v = tanhf(gii - gij - gji + gjj);
        s_tbl[i * NUM_AA + j] = v;
        s_tbl[j * NUM_AA + i] = v;
    }
    __syncthreads();

    // Batched ILP-4 gather: 8 independent LDG.128 in flight per thread.
    const int stride = gridDim.x * THREADS;
    int p = blockIdx.x * THREADS + t;

    for (; p + 3 * stride < n4; p += 4 * stride) {
        int4 a0 = idx_i4[p];
        int4 a1 = idx_i4[p + stride];
        int4 a2 = idx_i4[p + 2 * stride];
        int4 a3 = idx_i4[p + 3 * stride];
        int4 b0 = idx_j4[p];
        int4 b1 = idx_j4[p + stride];
        int4 b2 = idx_j4[p + 2 * stride];
        int4 b3 = idx_j4[p + 3 * stride];
        float4 o;
        o.x = s_tbl[a0.x * NUM_AA + b0.x];
        o.y = s_tbl[a0.y * NUM_AA + b0.y];
        o.z = s_tbl[a0.z * NUM_AA + b0.z];
        o.w = s_tbl[a0.w * NUM_AA + b0.w];
        out4[p] = o;
        o.x = s_tbl[a1.x * NUM_AA + b1.x];
        o.y = s_tbl[a1.y * NUM_AA + b1.y];
        o.z = s_tbl[a1.z * NUM_AA + b1.z];
        o.w = s_tbl[a1.w * NUM_AA + b1.w];
        out4[p + stride] = o;
        o.x = s_tbl[a2.x * NUM_AA + b2.x];
        o.y = s_tbl[a2.y * NUM_AA + b2.y];
        o.z = s_tbl[a2.z * NUM_AA + b2.z];
        o.w = s_tbl[a2.w * NUM_AA + b2.w];
        out4[p + 2 * stride] = o;
        o.x = s_tbl[a3.x * NUM_AA + b3.x];
        o.y = s_tbl[a3.y * NUM_AA + b3.y];
        o.z = s_tbl[a3.z * NUM_AA + b3.z];
        o.w = s_tbl[a3.w * NUM_AA + b3.w];
        out4[p + 3 * stride] = o;
    }
    for (; p < n4; p += stride) {
        int4 a = idx_i4[p];
        int4 b = idx_j4[p];
        float4 o;
        o.x = s_tbl[a.x * NUM_AA + b.x];
        o.y = s_tbl[a.y * NUM_AA + b.y];
        o.z = s_tbl[a.z * NUM_AA + b.z];
        o.w = s_tbl[a.w * NUM_AA + b.w];
        out4[p] = o;
    }
}

extern "C" void kernel_launch(void* const* d_in, const int* in_sizes, int n_in,
                              void* d_out, int out_size)
{
    const float* features = (const float*)d_in[0];   // [20,16]
    const float* M        = (const float*)d_in[1];   // [16,16]
    const int*   idx_i    = (const int*)d_in[2];     // [P]
    const int*   idx_j    = (const int*)d_in[3];     // [P]
    float*       out      = (float*)d_out;           // [P]

    const int P  = out_size;   // 8,388,608
    const int n4 = P / 4;      // 2,097,152

    static int blocks = 0;
    if (blocks == 0) {
        int per_sm = 0;
        cudaOccupancyMaxActiveBlocksPerMultiprocessor(
            &per_sm, snack_fused_kernel, THREADS, 0);
        if (per_sm < 1) per_sm = 1;
        int sms = 0;
        cudaDeviceGetAttribute(&sms, cudaDevAttrMultiProcessorCount, 0);
        if (sms <= 0) sms = 148;
        blocks = per_sm * sms;
        int max_blocks = (n4 + THREADS - 1) / THREADS;
        if (blocks > max_blocks) blocks = max_blocks;
    }

    snack_fused_kernel<<<blocks, THREADS>>>(
        features, M,
        (const int4*)idx_i, (const int4*)idx_j,
        (float4*)out, n4);
}